// round 3
// baseline (speedup 1.0000x reference)
#include <cuda_runtime.h>
#include <cstdint>

#define MAXN 50000
#define MAXE 1600000
#define D 64

// Scratch (no allocations allowed): ~26 MB of __device__ globals.
__device__ float g_hmu[MAXN * D];    // relu(mu @ W3^T)
__device__ float g_agg[MAXN * D];    // segment-sum of h_mu[dst] over src
__device__ float g_Sx[MAXN * 4];     // per-node scalar sums: Spos, Sneg, Sw, pad
__device__ float g_v[3 * D];         // v1=W4a@relu(W1), v1n=W4a@relu(-W1), v2=W4b@relu(W2)

__device__ __forceinline__ void red_add_v4(float* addr, float4 v) {
    asm volatile("red.global.add.v4.f32 [%0], {%1,%2,%3,%4};"
                 :: "l"(addr), "f"(v.x), "f"(v.y), "f"(v.z), "f"(v.w)
                 : "memory");
}

// K0: zero the accumulators (no runtime APIs allowed in kernel_launch).
__global__ __launch_bounds__(256) void k_zero(int N) {
    int total4 = (N * D + N * 4) >> 2;       // g_agg then g_Sx, both float4-aligned
    int stride = gridDim.x * blockDim.x;
    float4 z = make_float4(0.f, 0.f, 0.f, 0.f);
    int nagg4 = (N * D) >> 2;
    for (int i = blockIdx.x * blockDim.x + threadIdx.x; i < total4; i += stride) {
        if (i < nagg4) ((float4*)g_agg)[i] = z;
        else           ((float4*)g_Sx)[i - nagg4] = z;
    }
}

// K1: h_mu[n,o] = relu(sum_k mu[n,k] * W3[o,k]).  4 nodes per 256-thread block.
__global__ __launch_bounds__(256) void k_hmu(const float* __restrict__ mu,
                                             const float* __restrict__ W3, int N) {
    __shared__ float sW3[64 * 65];   // padded: conflict-free row reads
    for (int i = threadIdx.x; i < 64 * 64; i += blockDim.x) {
        int r = i >> 6, c = i & 63;
        sW3[r * 65 + c] = W3[i];
    }
    __syncthreads();
    int n = blockIdx.x * 4 + (threadIdx.x >> 6);
    int o = threadIdx.x & 63;
    if (n >= N) return;
    const float4* murow = (const float4*)(mu + (size_t)n * D);
    float acc = 0.f;
#pragma unroll
    for (int k4 = 0; k4 < 16; k4++) {
        float4 m = murow[k4];
        const float* w = &sW3[o * 65 + k4 * 4];
        acc = fmaf(m.x, w[0], acc);
        acc = fmaf(m.y, w[1], acc);
        acc = fmaf(m.z, w[2], acc);
        acc = fmaf(m.w, w[3], acc);
    }
    g_hmu[(size_t)n * D + o] = fmaxf(acc, 0.f);
}

// Tiny: precompute the three rank-1 vectors.
__global__ void k_vprep(const float* __restrict__ W1, const float* __restrict__ W2,
                        const float* __restrict__ W4) {
    int o = threadIdx.x;  // 64 threads
    float a = 0.f, b = 0.f, c = 0.f;
#pragma unroll 8
    for (int k = 0; k < 64; k++) {
        float w4a = W4[o * 192 + k];
        float w4b = W4[o * 192 + 64 + k];
        float w1 = W1[k], w2 = W2[k];
        a = fmaf(w4a, fmaxf(w1, 0.f), a);
        b = fmaf(w4a, fmaxf(-w1, 0.f), b);
        c = fmaf(w4b, fmaxf(w2, 0.f), c);
    }
    g_v[o] = a;
    g_v[64 + o] = b;
    g_v[128 + o] = c;
}

// K2: per-edge scatter. 16 threads per edge: each moves one float4 of h_mu[dst]
// into agg[src] via vector red. Lane 0 also reduces the 3 scalars.
// edge_index is int32 (JAX default config demotes int64 -> int32).
__global__ __launch_bounds__(256) void k_edge(const int* __restrict__ ei,
                                              const float* __restrict__ x,
                                              const float* __restrict__ ew,
                                              int E, int N) {
    long long t = (long long)blockIdx.x * blockDim.x + threadIdx.x;
    int e = (int)(t >> 4);
    if (e >= E) return;
    int j = (int)(t & 15);
    int src = ei[e];                    // scatter side (segment id)
    int dst = ei[(size_t)E + e];        // gather side
    if ((unsigned)src >= (unsigned)N || (unsigned)dst >= (unsigned)N) return;  // safety
    float4 v = ((const float4*)g_hmu)[(size_t)dst * 16 + j];
    red_add_v4(&g_agg[(size_t)src * 64 + (size_t)j * 4], v);
    if (j == 0) {
        float xd = x[dst];
        float w = ew[e];
        float4 s = make_float4(fmaxf(xd, 0.f), fmaxf(-xd, 0.f), w, 0.f);
        red_add_v4(&g_Sx[(size_t)src * 4], s);
    }
}

// K4: finalize. z = Spos*v1 + Sneg*v1n + Sw*v2 + agg_mu @ W4c^T;
//     out = relu(hx + hmu + relu(z))
__global__ __launch_bounds__(256) void k_final(const float* __restrict__ x,
                                               const float* __restrict__ W1,
                                               const float* __restrict__ W4,
                                               float* __restrict__ out, int N) {
    __shared__ float sW4c[64 * 65];
    __shared__ float sv[3 * 64];
    __shared__ float sW1[64];
    for (int i = threadIdx.x; i < 64 * 64; i += blockDim.x) {
        int r = i >> 6, c = i & 63;
        sW4c[r * 65 + c] = W4[r * 192 + 128 + c];
    }
    for (int i = threadIdx.x; i < 192; i += blockDim.x) sv[i] = g_v[i];
    for (int i = threadIdx.x; i < 64; i += blockDim.x) sW1[i] = W1[i];
    __syncthreads();
    int n = blockIdx.x * 4 + (threadIdx.x >> 6);
    int o = threadIdx.x & 63;
    if (n >= N) return;
    float Spos = g_Sx[(size_t)n * 4 + 0];
    float Sneg = g_Sx[(size_t)n * 4 + 1];
    float Sw   = g_Sx[(size_t)n * 4 + 2];
    float z = Spos * sv[o] + Sneg * sv[64 + o] + Sw * sv[128 + o];
    const float4* ar = (const float4*)(g_agg + (size_t)n * 64);
#pragma unroll
    for (int k4 = 0; k4 < 16; k4++) {
        float4 a = ar[k4];
        const float* w = &sW4c[o * 65 + k4 * 4];
        z = fmaf(a.x, w[0], z);
        z = fmaf(a.y, w[1], z);
        z = fmaf(a.z, w[2], z);
        z = fmaf(a.w, w[3], z);
    }
    float agg = fmaxf(z, 0.f);
    float hx = fmaxf(x[n] * sW1[o], 0.f);
    out[(size_t)n * 64 + o] = fmaxf(hx + g_hmu[(size_t)n * 64 + o] + agg, 0.f);
}

extern "C" void kernel_launch(void* const* d_in, const int* in_sizes, int n_in,
                              void* d_out, int out_size) {
    const float* mu  = (const float*)d_in[0];
    const float* x   = (const float*)d_in[1];
    const int*   ei  = (const int*)d_in[2];     // int32 (JAX x64 disabled)
    const float* ew  = (const float*)d_in[3];
    const float* W1  = (const float*)d_in[4];
    const float* W2  = (const float*)d_in[5];
    const float* W3  = (const float*)d_in[6];
    const float* W4  = (const float*)d_in[7];
    float* out = (float*)d_out;

    int N = in_sizes[1];   // x: [N,1]
    int E = in_sizes[3];   // edge_w: [E]

    k_zero<<<256, 256>>>(N);
    k_hmu<<<(N + 3) / 4, 256>>>(mu, W3, N);
    k_vprep<<<1, 64>>>(W1, W2, W4);

    long long total = (long long)E * 16;
    int blocks = (int)((total + 255) / 256);
    k_edge<<<blocks, 256>>>(ei, x, ew, E, N);

    k_final<<<(N + 3) / 4, 256>>>(x, W1, W4, out, N);
}

// round 4
// speedup vs baseline: 1.0188x; 1.0188x over previous
#include <cuda_runtime.h>
#include <cstdint>

#define MAXN 50000
#define MAXE 1600000
#define D 64

// ---- scratch (__device__ globals; no allocations allowed) ----
__device__ int   g_cnt[MAXN];        // per-src degree
__device__ int   g_pos[MAXN];        // placement cursor
__device__ int   g_rowstart[MAXN];   // exclusive prefix of g_cnt
__device__ int   g_bsum[256];        // scan partials
__device__ int   g_boff[256];        // scanned partials
__device__ int   g_edst[MAXE];       // dst sorted by src
__device__ float g_ews[MAXE];        // edge_w sorted by src
__device__ float g_hmu[MAXN * D];    // relu(mu @ W3^T)
__device__ float g_v[3 * D];         // v1=W4a@relu(W1), v1n=W4a@relu(-W1), v2=W4b@relu(W2)

__device__ __forceinline__ float relu(float a) { return fmaxf(a, 0.f); }

// K0: zero counters
__global__ __launch_bounds__(256) void k_zero(int N) {
    int stride = gridDim.x * blockDim.x;
    for (int i = blockIdx.x * blockDim.x + threadIdx.x; i < N; i += stride) {
        g_cnt[i] = 0;
        g_pos[i] = 0;
    }
}

// K1: histogram of src
__global__ __launch_bounds__(256) void k_hist(const int* __restrict__ ei, int E) {
    int stride = gridDim.x * blockDim.x;
    for (int e = blockIdx.x * blockDim.x + threadIdx.x; e < E; e += stride)
        atomicAdd(&g_cnt[ei[e]], 1);
}

// K2a: per-block exclusive scan of g_cnt (256 elems/block), block sums to g_bsum
__global__ __launch_bounds__(256) void k_scan1(int N) {
    __shared__ int s[256];
    int t = threadIdx.x;
    int i = blockIdx.x * 256 + t;
    int v = (i < N) ? g_cnt[i] : 0;
    s[t] = v;
    __syncthreads();
#pragma unroll
    for (int off = 1; off < 256; off <<= 1) {
        int add = (t >= off) ? s[t - off] : 0;
        __syncthreads();
        s[t] += add;
        __syncthreads();
    }
    int incl = s[t];
    if (i < N) g_rowstart[i] = incl - v;
    if (t == 255) g_bsum[blockIdx.x] = incl;
}

// K2b: scan the block sums (single block; nb <= 256)
__global__ __launch_bounds__(256) void k_scan2(int nb) {
    __shared__ int s[256];
    int t = threadIdx.x;
    int v = (t < nb) ? g_bsum[t] : 0;
    s[t] = v;
    __syncthreads();
#pragma unroll
    for (int off = 1; off < 256; off <<= 1) {
        int add = (t >= off) ? s[t - off] : 0;
        __syncthreads();
        s[t] += add;
        __syncthreads();
    }
    g_boff[t] = s[t] - v;   // exclusive
}

// K2c: add block offsets
__global__ __launch_bounds__(256) void k_scan3(int N) {
    int i = blockIdx.x * 256 + threadIdx.x;
    if (i < N) g_rowstart[i] += g_boff[i >> 8];
}

// K3: place edges into CSR slots, storing dst and ew directly
__global__ __launch_bounds__(256) void k_place(const int* __restrict__ ei,
                                               const float* __restrict__ ew, int E) {
    int stride = gridDim.x * blockDim.x;
    for (int e = blockIdx.x * blockDim.x + threadIdx.x; e < E; e += stride) {
        int src = ei[e];
        int dst = ei[(size_t)E + e];
        int slot = g_rowstart[src] + atomicAdd(&g_pos[src], 1);
        g_edst[slot] = dst;
        g_ews[slot]  = ew[e];
    }
}

// K4: h_mu = relu(mu @ W3^T). 16 nodes per 256-thread block; W3 transposed in smem.
__global__ __launch_bounds__(256) void k_hmu(const float* __restrict__ mu,
                                             const float* __restrict__ W3, int N) {
    __shared__ float  sW3t[64 * 64];   // [k][o]
    __shared__ float4 smu4[16 * 16];   // 16 node rows
    int t = threadIdx.x;
    for (int i = t; i < 64 * 64; i += 256) {
        int o = i >> 6, k = i & 63;
        sW3t[k * 64 + o] = W3[i];
    }
    int base = blockIdx.x * 16;
    {
        int g = t >> 4, q = t & 15;
        int n = base + g;
        float4 m = make_float4(0.f, 0.f, 0.f, 0.f);
        if (n < N) m = ((const float4*)mu)[(size_t)n * 16 + q];
        smu4[g * 16 + q] = m;
    }
    __syncthreads();
    int g = t >> 4, o4 = t & 15;
    int n = base + g;
    const float* smu = (const float*)smu4;
    float4 acc = make_float4(0.f, 0.f, 0.f, 0.f);
#pragma unroll
    for (int k = 0; k < 64; k++) {
        float m = smu[g * 64 + k];
        float4 w = ((const float4*)sW3t)[k * 16 + o4];
        acc.x = fmaf(m, w.x, acc.x);
        acc.y = fmaf(m, w.y, acc.y);
        acc.z = fmaf(m, w.z, acc.z);
        acc.w = fmaf(m, w.w, acc.w);
    }
    if (n < N) {
        float4 r = make_float4(relu(acc.x), relu(acc.y), relu(acc.z), relu(acc.w));
        ((float4*)g_hmu)[(size_t)n * 16 + o4] = r;
    }
}

// Tiny: the three rank-1 vectors
__global__ void k_vprep(const float* __restrict__ W1, const float* __restrict__ W2,
                        const float* __restrict__ W4) {
    int o = threadIdx.x;  // 64 threads
    float a = 0.f, b = 0.f, c = 0.f;
#pragma unroll 8
    for (int k = 0; k < 64; k++) {
        float w4a = W4[o * 192 + k];
        float w4b = W4[o * 192 + 64 + k];
        float w1 = W1[k], w2 = W2[k];
        a = fmaf(w4a, relu(w1), a);
        b = fmaf(w4a, relu(-w1), b);
        c = fmaf(w4b, relu(w2), c);
    }
    g_v[o] = a;
    g_v[64 + o] = b;
    g_v[128 + o] = c;
}

// K5: fused gather-reduce + finalize. 16 nodes per 256-thread block.
// Phase A: 16 threads/node gather h_mu[dst] float4s over the CSR neighbor list
//          (registers accumulate; no atomics), lane 0 reduces the 3 scalars.
// Phase B: 64x64 GEMV against W4c (transposed in smem) + rank-1 terms + epilogue.
__global__ __launch_bounds__(256) void k_node(const float* __restrict__ x,
                                              const float* __restrict__ W1,
                                              const float* __restrict__ W4,
                                              float* __restrict__ out, int N) {
    __shared__ float  sW4t[64 * 64];   // [k][o] of W4 cols 128..191
    __shared__ float4 sAgg4[16 * 16];
    __shared__ float  sSx[16 * 3];
    __shared__ float  sv[192];
    __shared__ float  sW1[64];
    int t = threadIdx.x;
    for (int i = t; i < 64 * 64; i += 256) {
        int o = i >> 6, k = i & 63;
        sW4t[k * 64 + o] = W4[o * 192 + 128 + k];
    }
    if (t < 192) sv[t] = g_v[t];
    if (t < 64)  sW1[t] = W1[t];

    int g = t >> 4, j = t & 15;
    int n = blockIdx.x * 16 + g;

    float4 acc = make_float4(0.f, 0.f, 0.f, 0.f);
    float sp = 0.f, sn = 0.f, sw = 0.f;
    if (n < N) {
        int deg = g_cnt[n];
        int start = g_rowstart[n];
        const float4* hmu4 = (const float4*)g_hmu;
        for (int i = 0; i < deg; i++) {
            int dst = g_edst[start + i];                 // sequential, L1-friendly
            float4 v = hmu4[(size_t)dst * 16 + j];       // 256B contiguous per group
            acc.x += v.x; acc.y += v.y; acc.z += v.z; acc.w += v.w;
            if (j == 0) {
                float xd = x[dst];
                sp += relu(xd);
                sn += relu(-xd);
                sw += g_ews[start + i];
            }
        }
    }
    sAgg4[g * 16 + j] = acc;
    if (j == 0) { sSx[g * 3 + 0] = sp; sSx[g * 3 + 1] = sn; sSx[g * 3 + 2] = sw; }
    __syncthreads();

    // Phase B: thread t computes 4 outputs (o4*4 .. +3) of node g
    int o4 = j;
    int o0 = o4 * 4;
    float Sp = sSx[g * 3 + 0], Sn = sSx[g * 3 + 1], Sw = sSx[g * 3 + 2];
    const float* sAgg = (const float*)sAgg4;
    float4 z;
    z.x = Sp * sv[o0 + 0] + Sn * sv[64 + o0 + 0] + Sw * sv[128 + o0 + 0];
    z.y = Sp * sv[o0 + 1] + Sn * sv[64 + o0 + 1] + Sw * sv[128 + o0 + 1];
    z.z = Sp * sv[o0 + 2] + Sn * sv[64 + o0 + 2] + Sw * sv[128 + o0 + 2];
    z.w = Sp * sv[o0 + 3] + Sn * sv[64 + o0 + 3] + Sw * sv[128 + o0 + 3];
#pragma unroll
    for (int k = 0; k < 64; k++) {
        float a = sAgg[g * 64 + k];
        float4 w = ((const float4*)sW4t)[k * 16 + o4];
        z.x = fmaf(a, w.x, z.x);
        z.y = fmaf(a, w.y, z.y);
        z.z = fmaf(a, w.z, z.z);
        z.w = fmaf(a, w.w, z.w);
    }
    if (n < N) {
        float xn = x[n];
        float4 hm = ((const float4*)g_hmu)[(size_t)n * 16 + o4];
        float4 r;
        r.x = relu(relu(xn * sW1[o0 + 0]) + hm.x + relu(z.x));
        r.y = relu(relu(xn * sW1[o0 + 1]) + hm.y + relu(z.y));
        r.z = relu(relu(xn * sW1[o0 + 2]) + hm.z + relu(z.z));
        r.w = relu(relu(xn * sW1[o0 + 3]) + hm.w + relu(z.w));
        ((float4*)out)[(size_t)n * 16 + o4] = r;
    }
}

extern "C" void kernel_launch(void* const* d_in, const int* in_sizes, int n_in,
                              void* d_out, int out_size) {
    const float* mu  = (const float*)d_in[0];
    const float* x   = (const float*)d_in[1];
    const int*   ei  = (const int*)d_in[2];     // int32 (JAX x64 disabled)
    const float* ew  = (const float*)d_in[3];
    const float* W1  = (const float*)d_in[4];
    const float* W2  = (const float*)d_in[5];
    const float* W3  = (const float*)d_in[6];
    const float* W4  = (const float*)d_in[7];
    float* out = (float*)d_out;

    int N = in_sizes[1];   // x: [N,1]
    int E = in_sizes[3];   // edge_w: [E]
    int nb = (N + 255) / 256;          // scan partial blocks (<= 256 for N <= 65536)

    k_zero<<<128, 256>>>(N);
    k_hist<<<(E + 255) / 256, 256>>>(ei, E);
    k_scan1<<<nb, 256>>>(N);
    k_scan2<<<1, 256>>>(nb);
    k_scan3<<<nb, 256>>>(N);
    k_place<<<(E + 255) / 256, 256>>>(ei, ew, E);

    k_hmu<<<(N + 15) / 16, 256>>>(mu, W3, N);
    k_vprep<<<1, 64>>>(W1, W2, W4);

    k_node<<<(N + 15) / 16, 256>>>(x, W1, W4, out, N);
}